// round 3
// baseline (speedup 1.0000x reference)
#include <cuda_runtime.h>
#include <cuda_bf16.h>
#include <math.h>

// Problem constants (fixed for this instance)
#define HID   512
#define NH    8
#define HD    64
#define BQ    2048   // query length
#define BB    2      // batch
#define SSQ   4096   // side length
#define TOPK  64
#define NEGV  (-1e9f)

// -------- scratch (device globals; no allocation) --------
__device__ float g_q[(size_t)BB * BQ * HID];     // 8 MB
__device__ float g_k[(size_t)SSQ * HID];         // 8 MB
__device__ float g_v[(size_t)SSQ * HID];         // 8 MB
__device__ float g_ctx[(size_t)BB * BQ * HID];   // 8 MB
__device__ float g_scores[(size_t)BB * NH * BQ * SSQ];  // 512 MB

// ============================================================
// Generic SGEMM: C[M,512] = A[M,512] @ W[512,512] + bias
// 128x128 tile, BK=16, 256 threads, 8x8 micro-tile (4+4 split)
// ============================================================
__global__ void __launch_bounds__(256) sgemm_bias(
    const float* __restrict__ A, const float* __restrict__ W,
    const float* __restrict__ bias, float* __restrict__ C)
{
    __shared__ float As[16][132];   // transposed: As[k][m]
    __shared__ float Ws[16][132];   // Ws[k][n]

    const int tid = threadIdx.x;
    const int bm = blockIdx.y * 128;
    const int bn = blockIdx.x * 128;
    const int tm = tid >> 4;        // 0..15
    const int tn = tid & 15;        // 0..15

    float acc[8][8];
#pragma unroll
    for (int i = 0; i < 8; i++)
#pragma unroll
        for (int j = 0; j < 8; j++) acc[i][j] = 0.f;

    for (int k0 = 0; k0 < 512; k0 += 16) {
        // load A tile (128 rows x 16 k) transposed
#pragma unroll
        for (int it = 0; it < 2; it++) {
            int l = tid + it * 256;              // 0..511
            int r = l >> 2;
            int c4 = (l & 3) * 4;
            float4 av = *(const float4*)(A + (size_t)(bm + r) * 512 + k0 + c4);
            As[c4 + 0][r] = av.x;
            As[c4 + 1][r] = av.y;
            As[c4 + 2][r] = av.z;
            As[c4 + 3][r] = av.w;
        }
        // load W tile (16 k x 128 n)
#pragma unroll
        for (int it = 0; it < 2; it++) {
            int l = tid + it * 256;
            int kr = l >> 5;
            int c4 = (l & 31) * 4;
            *(float4*)&Ws[kr][c4] =
                *(const float4*)(W + (size_t)(k0 + kr) * 512 + bn + c4);
        }
        __syncthreads();

#pragma unroll
        for (int k = 0; k < 16; k++) {
            float ra[8], rb[8];
            *(float4*)&ra[0] = *(float4*)&As[k][tm * 4];
            *(float4*)&ra[4] = *(float4*)&As[k][64 + tm * 4];
            *(float4*)&rb[0] = *(float4*)&Ws[k][tn * 4];
            *(float4*)&rb[4] = *(float4*)&Ws[k][64 + tn * 4];
#pragma unroll
            for (int i = 0; i < 8; i++)
#pragma unroll
                for (int j = 0; j < 8; j++)
                    acc[i][j] = fmaf(ra[i], rb[j], acc[i][j]);
        }
        __syncthreads();
    }

#pragma unroll
    for (int i = 0; i < 8; i++) {
        int r = bm + ((i < 4) ? (tm * 4 + i) : (64 + tm * 4 + (i - 4)));
#pragma unroll
        for (int jj = 0; jj < 2; jj++) {
            int c = bn + jj * 64 + tn * 4;
            float4 o;
            o.x = acc[i][jj * 4 + 0] + bias[c + 0];
            o.y = acc[i][jj * 4 + 1] + bias[c + 1];
            o.z = acc[i][jj * 4 + 2] + bias[c + 2];
            o.w = acc[i][jj * 4 + 3] + bias[c + 3];
            *(float4*)(C + (size_t)r * 512 + c) = o;
        }
    }
}

// ============================================================
// Scores: scores[b,h,q,s] = dot(q[b,q,h,:], k[s,h,:]) * 0.125
//                           + (mask? 0 : -1e9)
// grid: (S/128, Q/128, B*H); 128x128 tile over D=64 (two 32-chunks)
// ============================================================
__global__ void __launch_bounds__(256) scores_kernel(const int* __restrict__ mask)
{
    __shared__ float Qs[32][132];   // Qs[k][m]
    __shared__ float Ks[32][132];   // Ks[k][n]

    const int bh = blockIdx.z;
    const int b = bh >> 3;
    const int h = bh & 7;
    const int q0 = blockIdx.y * 128;
    const int s0 = blockIdx.x * 128;
    const int tid = threadIdx.x;
    const int tm = tid >> 4;
    const int tn = tid & 15;

    const float* qbase = g_q + (size_t)b * BQ * 512 + h * HD;
    const float* kbase = g_k + h * HD;

    float acc[8][8];
#pragma unroll
    for (int i = 0; i < 8; i++)
#pragma unroll
        for (int j = 0; j < 8; j++) acc[i][j] = 0.f;

    for (int kc = 0; kc < HD; kc += 32) {
        // Q tile: 128 rows x 32 cols, transposed store
#pragma unroll
        for (int it = 0; it < 4; it++) {
            int l = tid + it * 256;   // 0..1023
            int r = l >> 3;
            int c4 = (l & 7) * 4;
            float4 v = *(const float4*)(qbase + (size_t)(q0 + r) * 512 + kc + c4);
            Qs[c4 + 0][r] = v.x;
            Qs[c4 + 1][r] = v.y;
            Qs[c4 + 2][r] = v.z;
            Qs[c4 + 3][r] = v.w;
        }
#pragma unroll
        for (int it = 0; it < 4; it++) {
            int l = tid + it * 256;
            int r = l >> 3;
            int c4 = (l & 7) * 4;
            float4 v = *(const float4*)(kbase + (size_t)(s0 + r) * 512 + kc + c4);
            Ks[c4 + 0][r] = v.x;
            Ks[c4 + 1][r] = v.y;
            Ks[c4 + 2][r] = v.z;
            Ks[c4 + 3][r] = v.w;
        }
        __syncthreads();

#pragma unroll
        for (int k = 0; k < 32; k++) {
            float ra[8], rb[8];
            *(float4*)&ra[0] = *(float4*)&Qs[k][tm * 4];
            *(float4*)&ra[4] = *(float4*)&Qs[k][64 + tm * 4];
            *(float4*)&rb[0] = *(float4*)&Ks[k][tn * 4];
            *(float4*)&rb[4] = *(float4*)&Ks[k][64 + tn * 4];
#pragma unroll
            for (int i = 0; i < 8; i++)
#pragma unroll
                for (int j = 0; j < 8; j++)
                    acc[i][j] = fmaf(ra[i], rb[j], acc[i][j]);
        }
        __syncthreads();
    }

    float* sbase = g_scores + (size_t)bh * BQ * SSQ;
    const int* mbase = mask + (size_t)b * BQ * SSQ;
#pragma unroll
    for (int i = 0; i < 8; i++) {
        int r = q0 + ((i < 4) ? (tm * 4 + i) : (64 + tm * 4 + (i - 4)));
#pragma unroll
        for (int jj = 0; jj < 2; jj++) {
            int c = s0 + jj * 64 + tn * 4;
            int4 m4 = *(const int4*)(mbase + (size_t)r * SSQ + c);
            float4 o;
            o.x = acc[i][jj * 4 + 0] * 0.125f + (m4.x ? 0.f : NEGV);
            o.y = acc[i][jj * 4 + 1] * 0.125f + (m4.y ? 0.f : NEGV);
            o.z = acc[i][jj * 4 + 2] * 0.125f + (m4.z ? 0.f : NEGV);
            o.w = acc[i][jj * 4 + 3] * 0.125f + (m4.w ? 0.f : NEGV);
            *(float4*)(sbase + (size_t)r * SSQ + c) = o;
        }
    }
}

// ============================================================
// Top-k (exact radix select) + softmax + ctx gather
// one block (256 thr) per score row; 16 values per thread
// ============================================================
__global__ void __launch_bounds__(256) topk_ctx_kernel()
{
    const size_t row = blockIdx.x;          // ((b*8+h)*2048 + q)
    const int q = (int)(row & 2047);
    const int bh = (int)(row >> 11);
    const int h = bh & 7;
    const int b = bh >> 3;

    const float* srow = g_scores + row * SSQ;
    const int tid = threadIdx.x;

    __shared__ float red[256];
    __shared__ unsigned hist[256];
    __shared__ unsigned scan[256];
    __shared__ unsigned sh_prefix, sh_want;
    __shared__ int cnt;
    __shared__ int sidx[512];
    __shared__ float sp[512];
    __shared__ float ctxs[4][64];

    // ---- load row, compute sortable keys + local max ----
    float val[16];
    unsigned u[16];
    float lmax = -INFINITY;
#pragma unroll
    for (int i = 0; i < 16; i++) {
        float x = srow[tid + i * 256];
        val[i] = x;
        unsigned bits = __float_as_uint(x);
        u[i] = (bits & 0x80000000u) ? ~bits : (bits | 0x80000000u);
        lmax = fmaxf(lmax, x);
    }

    // block max
    red[tid] = lmax;
    __syncthreads();
    for (int o = 128; o > 0; o >>= 1) {
        if (tid < o) red[tid] = fmaxf(red[tid], red[tid + o]);
        __syncthreads();
    }
    const float rowmax = red[0];
    __syncthreads();

    // ---- radix select: 64th largest key ----
    if (tid == 0) { sh_prefix = 0u; sh_want = TOPK; cnt = 0; }
    unsigned maskbits = 0u;
    __syncthreads();

    for (int pass = 0; pass < 4; pass++) {
        const int shift = 24 - 8 * pass;
        hist[tid] = 0u;
        __syncthreads();
        const unsigned prefix = sh_prefix;
#pragma unroll
        for (int i = 0; i < 16; i++)
            if ((u[i] & maskbits) == prefix)
                atomicAdd(&hist[(u[i] >> shift) & 255u], 1u);
        __syncthreads();

        // descending cumulative count via inclusive prefix sum of reversed hist
        scan[tid] = hist[255 - tid];
        __syncthreads();
        for (int o = 1; o < 256; o <<= 1) {
            unsigned add = (tid >= o) ? scan[tid - o] : 0u;
            __syncthreads();
            scan[tid] += add;
            __syncthreads();
        }
        const unsigned want = sh_want;
        const unsigned cum = scan[tid];
        const unsigned prev = (tid == 0) ? 0u : scan[tid - 1];
        __syncthreads();
        if (cum >= want && prev < want) {
            sh_prefix = prefix | ((255u - (unsigned)tid) << shift);
            sh_want = want - prev;
        }
        maskbits |= (0xFFu << shift);
        __syncthreads();
    }
    const unsigned thresh_u = sh_prefix;

    // ---- softmax over selected entries (all others are exactly 0) ----
    float lsum = 0.f;
#pragma unroll
    for (int i = 0; i < 16; i++) {
        if (u[i] >= thresh_u) {
            float p = expf(val[i] - rowmax);
            lsum += p;
            int pos = atomicAdd(&cnt, 1);
            if (pos < 512) { sidx[pos] = tid + i * 256; sp[pos] = p; }
        }
    }
    red[tid] = lsum;
    __syncthreads();
    for (int o = 128; o > 0; o >>= 1) {
        if (tid < o) red[tid] += red[tid + o];
        __syncthreads();
    }
    const float invd = 1.0f / red[0];

    // ---- ctx = sum_sel p * v[s, h, :] ----
    const int g = tid >> 6;
    const int d = tid & 63;
    ctxs[g][d] = 0.f;
    __syncthreads();
    const int n = (cnt < 512) ? cnt : 512;
    const float* vh = g_v + h * HD;
    float a = 0.f;
    for (int e = g; e < n; e += 4)
        a += sp[e] * vh[(size_t)sidx[e] * 512 + d];
    ctxs[g][d] = a;
    __syncthreads();

    if (tid < 64) {
        float r2 = (ctxs[0][tid] + ctxs[1][tid] + ctxs[2][tid] + ctxs[3][tid]) * invd;
        g_ctx[((size_t)(b * BQ + q)) * 512 + h * HD + tid] = r2;
    }
}

// ============================================================
// host launcher
// ============================================================
extern "C" void kernel_launch(void* const* d_in, const int* in_sizes, int n_in,
                              void* d_out, int out_size)
{
    const float* main_in = (const float*)d_in[0];
    const float* side_in = (const float*)d_in[1];
    const int*   mask    = (const int*)d_in[2];
    const float* Wq = (const float*)d_in[3];
    const float* bq = (const float*)d_in[4];
    const float* Wk = (const float*)d_in[5];
    const float* bk = (const float*)d_in[6];
    const float* Wv = (const float*)d_in[7];
    const float* bv = (const float*)d_in[8];
    const float* Wo = (const float*)d_in[9];
    const float* bo = (const float*)d_in[10];
    float* out = (float*)d_out;

    float *pq, *pk, *pv, *pctx;
    cudaGetSymbolAddress((void**)&pq, g_q);
    cudaGetSymbolAddress((void**)&pk, g_k);
    cudaGetSymbolAddress((void**)&pv, g_v);
    cudaGetSymbolAddress((void**)&pctx, g_ctx);

    dim3 gB(512 / 128, (BB * BQ) / 128);   // (4, 32)

    // projections (M = 4096 for all three)
    sgemm_bias<<<gB, 256>>>(main_in, Wq, bq, pq);
    sgemm_bias<<<gB, 256>>>(side_in, Wk, bk, pk);
    sgemm_bias<<<gB, 256>>>(side_in, Wv, bv, pv);

    // masked scaled scores -> g_scores
    scores_kernel<<<dim3(SSQ / 128, BQ / 128, BB * NH), 256>>>(mask);

    // exact top-64 + softmax + ctx gather -> g_ctx
    topk_ctx_kernel<<<BB * NH * BQ, 256>>>();

    // output projection -> d_out
    sgemm_bias<<<gB, 256>>>(pctx, Wo, bo, out);
}

// round 6
// speedup vs baseline: 1.0129x; 1.0129x over previous
#include <cuda_runtime.h>
#include <cuda_bf16.h>
#include <math.h>
#include <stdint.h>

// Problem constants (fixed for this instance)
#define HID   512
#define NH    8
#define HD    64
#define BQ    2048   // query length
#define BB    2      // batch
#define SSQ   4096   // side length
#define TOPK  64
#define NEGV  (-1e9f)

// -------- scratch (device globals; no allocation) --------
__device__ float g_q[(size_t)BB * BQ * HID];     // 8 MB
__device__ float g_k[(size_t)SSQ * HID];         // 8 MB
__device__ float g_v[(size_t)SSQ * HID];         // 8 MB
__device__ float g_ctx[(size_t)BB * BQ * HID];   // 8 MB
__device__ float g_scores[(size_t)BB * NH * BQ * SSQ];  // 512 MB
// tf32 2-way splits of q and k (values are tf32-rounded, stored as fp32)
__device__ float g_qhi[(size_t)BB * BQ * HID];
__device__ float g_qlo[(size_t)BB * BQ * HID];
__device__ float g_khi[(size_t)SSQ * HID];
__device__ float g_klo[(size_t)SSQ * HID];

// ============================================================
// tf32 helpers (baseline PTX, valid on plain sm_103)
// ============================================================
__device__ __forceinline__ uint32_t tf32_rna(float x) {
    uint32_t r;
    asm("cvt.rna.tf32.f32 %0, %1;" : "=r"(r) : "r"(__float_as_uint(x)));
    return r;
}

// D += A*B  (m16n8k8, tf32 inputs, fp32 accum) — tensor pipe
__device__ __forceinline__ void mma_tf32(float c[4],
                                         const uint32_t a[4],
                                         const uint32_t b[2]) {
    asm volatile(
        "mma.sync.aligned.m16n8k8.row.col.f32.tf32.tf32.f32 "
        "{%0,%1,%2,%3}, {%4,%5,%6,%7}, {%8,%9}, {%0,%1,%2,%3};"
        : "+f"(c[0]), "+f"(c[1]), "+f"(c[2]), "+f"(c[3])
        : "r"(a[0]), "r"(a[1]), "r"(a[2]), "r"(a[3]),
          "r"(b[0]), "r"(b[1]));
}

// ============================================================
// Generic SGEMM: C[M,512] = A[M,512] @ W[512,512] + bias
// (known-good SIMT version; projections)
// ============================================================
__global__ void __launch_bounds__(256) sgemm_bias(
    const float* __restrict__ A, const float* __restrict__ W,
    const float* __restrict__ bias, float* __restrict__ C)
{
    __shared__ float As[16][132];
    __shared__ float Ws[16][132];

    const int tid = threadIdx.x;
    const int bm = blockIdx.y * 128;
    const int bn = blockIdx.x * 128;
    const int tm = tid >> 4;
    const int tn = tid & 15;

    float acc[8][8];
#pragma unroll
    for (int i = 0; i < 8; i++)
#pragma unroll
        for (int j = 0; j < 8; j++) acc[i][j] = 0.f;

    for (int k0 = 0; k0 < 512; k0 += 16) {
#pragma unroll
        for (int it = 0; it < 2; it++) {
            int l = tid + it * 256;
            int r = l >> 2;
            int c4 = (l & 3) * 4;
            float4 av = *(const float4*)(A + (size_t)(bm + r) * 512 + k0 + c4);
            As[c4 + 0][r] = av.x;
            As[c4 + 1][r] = av.y;
            As[c4 + 2][r] = av.z;
            As[c4 + 3][r] = av.w;
        }
#pragma unroll
        for (int it = 0; it < 2; it++) {
            int l = tid + it * 256;
            int kr = l >> 5;
            int c4 = (l & 31) * 4;
            *(float4*)&Ws[kr][c4] =
                *(const float4*)(W + (size_t)(k0 + kr) * 512 + bn + c4);
        }
        __syncthreads();

#pragma unroll
        for (int k = 0; k < 16; k++) {
            float ra[8], rb[8];
            *(float4*)&ra[0] = *(float4*)&As[k][tm * 4];
            *(float4*)&ra[4] = *(float4*)&As[k][64 + tm * 4];
            *(float4*)&rb[0] = *(float4*)&Ws[k][tn * 4];
            *(float4*)&rb[4] = *(float4*)&Ws[k][64 + tn * 4];
#pragma unroll
            for (int i = 0; i < 8; i++)
#pragma unroll
                for (int j = 0; j < 8; j++)
                    acc[i][j] = fmaf(ra[i], rb[j], acc[i][j]);
        }
        __syncthreads();
    }

#pragma unroll
    for (int i = 0; i < 8; i++) {
        int r = bm + ((i < 4) ? (tm * 4 + i) : (64 + tm * 4 + (i - 4)));
#pragma unroll
        for (int jj = 0; jj < 2; jj++) {
            int c = bn + jj * 64 + tn * 4;
            float4 o;
            o.x = acc[i][jj * 4 + 0] + bias[c + 0];
            o.y = acc[i][jj * 4 + 1] + bias[c + 1];
            o.z = acc[i][jj * 4 + 2] + bias[c + 2];
            o.w = acc[i][jj * 4 + 3] + bias[c + 3];
            *(float4*)(C + (size_t)r * 512 + c) = o;
        }
    }
}

// ============================================================
// fp32 -> tf32 2-way split: hi = tf32(x), lo = tf32(x - hi)
// ============================================================
__global__ void __launch_bounds__(256) split2_kernel(
    const float* __restrict__ src,
    float* __restrict__ ohi, float* __restrict__ olo, int n4)
{
    int i = blockIdx.x * 256 + threadIdx.x;
    if (i >= n4) return;
    float4 x = ((const float4*)src)[i];
    float vs[4] = {x.x, x.y, x.z, x.w};
    float hi[4], lo[4];
#pragma unroll
    for (int j = 0; j < 4; j++) {
        float h = __uint_as_float(tf32_rna(vs[j]));
        float l = __uint_as_float(tf32_rna(vs[j] - h));
        hi[j] = h; lo[j] = l;
    }
    ((float4*)ohi)[i] = make_float4(hi[0], hi[1], hi[2], hi[3]);
    ((float4*)olo)[i] = make_float4(lo[0], lo[1], lo[2], lo[3]);
}

// ============================================================
// Scores via mma.sync tf32 (3xTF32): D[128q,128s] = Q K^T
//   scores = D * 0.125 + (mask ? 0 : -1e9)
// grid (BB*NH, BQ/128), 256 threads (8 warps = 2m x 4n)
// smem: Qhi,Qlo,Khi,Klo each 128 x 64 (pad 68) fp32 = 139,264 B
// ============================================================
#define SPAD 68
#define SCORES_SMEM (4 * 128 * SPAD * 4)

__global__ void __launch_bounds__(256, 1) scores_mma(const int* __restrict__ mask)
{
    extern __shared__ float sm[];
    float* Qh = sm;
    float* Ql = Qh + 128 * SPAD;
    float* Kh = Ql + 128 * SPAD;
    float* Kl = Kh + 128 * SPAD;

    const int tid = threadIdx.x;
    const int wid = tid >> 5;
    const int lid = tid & 31;
    const int g   = lid >> 2;      // groupID 0..7
    const int tig = lid & 3;       // thread-in-group 0..3
    const int wm  = wid & 1;       // 2 m-groups of 64 rows
    const int wn  = wid >> 1;      // 4 n-groups of 32 cols

    const int bh = blockIdx.x;     // 0..15
    const int b  = bh >> 3;
    const int h  = bh & 7;
    const int q0 = blockIdx.y * 128;

    // ---- load Q hi/lo tiles (128 x 64 = 2048 float4 => 8 iters @256thr)
    {
        const float* qh = g_qhi + ((size_t)(b * BQ + q0)) * 512 + h * 64;
        const float* ql = g_qlo + ((size_t)(b * BQ + q0)) * 512 + h * 64;
#pragma unroll
        for (int it = 0; it < 8; it++) {
            int t = tid + it * 256;       // 0..2047
            int r = t >> 4;               // 0..127
            int c = (t & 15) * 4;         // 0..60
            *(float4*)&Qh[r * SPAD + c] = *(const float4*)(qh + (size_t)r * 512 + c);
            *(float4*)&Ql[r * SPAD + c] = *(const float4*)(ql + (size_t)r * 512 + c);
        }
    }

    const float* kh = g_khi + h * 64;
    const float* kl = g_klo + h * 64;
    float* srow0 = g_scores + ((size_t)bh * BQ + q0) * SSQ;
    const int* mrow0 = mask + ((size_t)b * BQ + q0) * SSQ;

    for (int st = 0; st < SSQ / 128; st++) {
        const int s0 = st * 128;

        __syncthreads();   // prev-iter fragment reads done before overwrite
#pragma unroll
        for (int it = 0; it < 8; it++) {
            int t = tid + it * 256;       // 0..2047
            int r = t >> 4;               // 0..127
            int c = (t & 15) * 4;
            *(float4*)&Kh[r * SPAD + c] =
                *(const float4*)(kh + (size_t)(s0 + r) * 512 + c);
            *(float4*)&Kl[r * SPAD + c] =
                *(const float4*)(kl + (size_t)(s0 + r) * 512 + c);
        }
        __syncthreads();

        float acc[4][4][4];
#pragma unroll
        for (int mt = 0; mt < 4; mt++)
#pragma unroll
            for (int nt = 0; nt < 4; nt++)
#pragma unroll
                for (int e = 0; e < 4; e++) acc[mt][nt][e] = 0.f;

#pragma unroll
        for (int kk = 0; kk < HD; kk += 8) {
            uint32_t ah[4][4], al[4][4], bhf[4][2], blf[4][2];
#pragma unroll
            for (int mt = 0; mt < 4; mt++) {
                const int r0 = (wm * 64 + mt * 16 + g) * SPAD + kk + tig;
                const int r8 = r0 + 8 * SPAD;
                ah[mt][0] = __float_as_uint(Qh[r0]);
                ah[mt][1] = __float_as_uint(Qh[r8]);
                ah[mt][2] = __float_as_uint(Qh[r0 + 4]);
                ah[mt][3] = __float_as_uint(Qh[r8 + 4]);
                al[mt][0] = __float_as_uint(Ql[r0]);
                al[mt][1] = __float_as_uint(Ql[r8]);
                al[mt][2] = __float_as_uint(Ql[r0 + 4]);
                al[mt][3] = __float_as_uint(Ql[r8 + 4]);
            }
#pragma unroll
            for (int nt = 0; nt < 4; nt++) {
                const int sr = (wn * 32 + nt * 8 + g) * SPAD + kk + tig;
                bhf[nt][0] = __float_as_uint(Kh[sr]);
                bhf[nt][1] = __float_as_uint(Kh[sr + 4]);
                blf[nt][0] = __float_as_uint(Kl[sr]);
                blf[nt][1] = __float_as_uint(Kl[sr + 4]);
            }
#pragma unroll
            for (int mt = 0; mt < 4; mt++)
#pragma unroll
                for (int nt = 0; nt < 4; nt++) {
                    mma_tf32(acc[mt][nt], ah[mt], bhf[nt]);   // hh
                    mma_tf32(acc[mt][nt], ah[mt], blf[nt]);   // hl
                    mma_tf32(acc[mt][nt], al[mt], bhf[nt]);   // lh
                }
        }

        // ---- epilogue: scale + mask + store (direct from C fragments)
#pragma unroll
        for (int mt = 0; mt < 4; mt++) {
            const int qr0 = wm * 64 + mt * 16 + g;
#pragma unroll
            for (int nt = 0; nt < 4; nt++) {
                const int col = s0 + wn * 32 + nt * 8 + tig * 2;
                {
                    const size_t off = (size_t)qr0 * SSQ + col;
                    int2 m2 = *(const int2*)(mrow0 + off);
                    float2 v;
                    v.x = acc[mt][nt][0] * 0.125f + (m2.x ? 0.f : NEGV);
                    v.y = acc[mt][nt][1] * 0.125f + (m2.y ? 0.f : NEGV);
                    *(float2*)(srow0 + off) = v;
                }
                {
                    const size_t off = (size_t)(qr0 + 8) * SSQ + col;
                    int2 m2 = *(const int2*)(mrow0 + off);
                    float2 v;
                    v.x = acc[mt][nt][2] * 0.125f + (m2.x ? 0.f : NEGV);
                    v.y = acc[mt][nt][3] * 0.125f + (m2.y ? 0.f : NEGV);
                    *(float2*)(srow0 + off) = v;
                }
            }
        }
    }
}

// ============================================================
// Top-k (exact radix select) + softmax + ctx gather (unchanged)
// ============================================================
__global__ void __launch_bounds__(256) topk_ctx_kernel()
{
    const size_t row = blockIdx.x;
    const int q = (int)(row & 2047);
    const int bh = (int)(row >> 11);
    const int h = bh & 7;
    const int b = bh >> 3;

    const float* srow = g_scores + row * SSQ;
    const int tid = threadIdx.x;

    __shared__ float red[256];
    __shared__ unsigned hist[256];
    __shared__ unsigned scan[256];
    __shared__ unsigned sh_prefix, sh_want;
    __shared__ int cnt;
    __shared__ int sidx[512];
    __shared__ float sp[512];
    __shared__ float ctxs[4][64];

    float val[16];
    unsigned u[16];
    float lmax = -INFINITY;
#pragma unroll
    for (int i = 0; i < 16; i++) {
        float x = srow[tid + i * 256];
        val[i] = x;
        unsigned bits = __float_as_uint(x);
        u[i] = (bits & 0x80000000u) ? ~bits : (bits | 0x80000000u);
        lmax = fmaxf(lmax, x);
    }

    red[tid] = lmax;
    __syncthreads();
    for (int o = 128; o > 0; o >>= 1) {
        if (tid < o) red[tid] = fmaxf(red[tid], red[tid + o]);
        __syncthreads();
    }
    const float rowmax = red[0];
    __syncthreads();

    if (tid == 0) { sh_prefix = 0u; sh_want = TOPK; cnt = 0; }
    unsigned maskbits = 0u;
    __syncthreads();

    for (int pass = 0; pass < 4; pass++) {
        const int shift = 24 - 8 * pass;
        hist[tid] = 0u;
        __syncthreads();
        const unsigned prefix = sh_prefix;
#pragma unroll
        for (int i = 0; i < 16; i++)
            if ((u[i] & maskbits) == prefix)
                atomicAdd(&hist[(u[i] >> shift) & 255u], 1u);
        __syncthreads();

        scan[tid] = hist[255 - tid];
        __syncthreads();
        for (int o = 1; o < 256; o <<= 1) {
            unsigned add = (tid >= o) ? scan[tid - o] : 0u;
            __syncthreads();
            scan[tid] += add;
            __syncthreads();
        }
        const unsigned want = sh_want;
        const unsigned cum = scan[tid];
        const unsigned prev = (tid == 0) ? 0u : scan[tid - 1];
        __syncthreads();
        if (cum >= want && prev < want) {
            sh_prefix = prefix | ((255u - (unsigned)tid) << shift);
            sh_want = want - prev;
        }
        maskbits |= (0xFFu << shift);
        __syncthreads();
    }
    const unsigned thresh_u = sh_prefix;

    float lsum = 0.f;
#pragma unroll
    for (int i = 0; i < 16; i++) {
        if (u[i] >= thresh_u) {
            float p = expf(val[i] - rowmax);
            lsum += p;
            int pos = atomicAdd(&cnt, 1);
            if (pos < 512) { sidx[pos] = tid + i * 256; sp[pos] = p; }
        }
    }
    red[tid] = lsum;
    __syncthreads();
    for (int o = 128; o > 0; o >>= 1) {
        if (tid < o) red[tid] += red[tid + o];
        __syncthreads();
    }
    const float invd = 1.0f / red[0];

    const int g = tid >> 6;
    const int d = tid & 63;
    ctxs[g][d] = 0.f;
    __syncthreads();
    const int n = (cnt < 512) ? cnt : 512;
    const float* vh = g_v + h * HD;
    float a = 0.f;
    for (int e = g; e < n; e += 4)
        a += sp[e] * vh[(size_t)sidx[e] * 512 + d];
    ctxs[g][d] = a;
    __syncthreads();

    if (tid < 64) {
        float r2 = (ctxs[0][tid] + ctxs[1][tid] + ctxs[2][tid] + ctxs[3][tid]) * invd;
        g_ctx[((size_t)(b * BQ + q)) * 512 + h * HD + tid] = r2;
    }
}

// ============================================================
// host launcher
// ============================================================
extern "C" void kernel_launch(void* const* d_in, const int* in_sizes, int n_in,
                              void* d_out, int out_size)
{
    const float* main_in = (const float*)d_in[0];
    const float* side_in = (const float*)d_in[1];
    const int*   mask    = (const int*)d_in[2];
    const float* Wq = (const float*)d_in[3];
    const float* bq = (const float*)d_in[4];
    const float* Wk = (const float*)d_in[5];
    const float* bk = (const float*)d_in[6];
    const float* Wv = (const float*)d_in[7];
    const float* bv = (const float*)d_in[8];
    const float* Wo = (const float*)d_in[9];
    const float* bo = (const float*)d_in[10];
    float* out = (float*)d_out;

    float *pq, *pk, *pv, *pctx;
    cudaGetSymbolAddress((void**)&pq, g_q);
    cudaGetSymbolAddress((void**)&pk, g_k);
    cudaGetSymbolAddress((void**)&pv, g_v);
    cudaGetSymbolAddress((void**)&pctx, g_ctx);
    float *pqh, *pql, *pkh, *pkl;
    cudaGetSymbolAddress((void**)&pqh, g_qhi);
    cudaGetSymbolAddress((void**)&pql, g_qlo);
    cudaGetSymbolAddress((void**)&pkh, g_khi);
    cudaGetSymbolAddress((void**)&pkl, g_klo);

    cudaFuncSetAttribute(scores_mma, cudaFuncAttributeMaxDynamicSharedMemorySize,
                         SCORES_SMEM);

    dim3 gB(512 / 128, (BB * BQ) / 128);   // (4, 32)

    // projections
    sgemm_bias<<<gB, 256>>>(main_in, Wq, bq, pq);
    sgemm_bias<<<gB, 256>>>(side_in, Wk, bk, pk);
    sgemm_bias<<<gB, 256>>>(side_in, Wv, bv, pv);

    // tf32 2-way splits of q and k
    {
        int n4q = (BB * BQ * HID) / 4;   // 524288
        int n4k = (SSQ * HID) / 4;       // 524288
        split2_kernel<<<(n4q + 255) / 256, 256>>>(pq, pqh, pql, n4q);
        split2_kernel<<<(n4k + 255) / 256, 256>>>(pk, pkh, pkl, n4k);
    }

    // masked scaled scores via tensor cores (3xTF32)
    scores_mma<<<dim3(BB * NH, BQ / 128), 256, SCORES_SMEM>>>(mask);

    // exact top-64 + softmax + ctx gather
    topk_ctx_kernel<<<BB * NH * BQ, 256>>>();

    // output projection
    sgemm_bias<<<gB, 256>>>(pctx, Wo, bo, out);
}